// round 12
// baseline (speedup 1.0000x reference)
#include <cuda_runtime.h>
#include <cstdint>

#define OUTP 7
#define CCH 256
#define NS 14                        // samples per axis
#define BINS 49
#define OUT_PER_BOX (CCH * BINS)     // 12544
#define CH_PER_CTA 16
#define NGROUPS (CCH / CH_PER_CTA)   // 16
#define THREADS 128
#define NWARPS (THREADS / 32)        // 4 warps -> 4*4 = 16 channels

__global__ __launch_bounds__(THREADS) void roi_pooler_kernel(
    const float* __restrict__ f0, const float* __restrict__ f1,
    const float* __restrict__ f2, const float* __restrict__ f3,
    const float* __restrict__ boxes, float* __restrict__ out)
{
    // Per-ph packed y-params: 4 row offsets (already *W) and 4 weights
    __shared__ int4   s_ro[OUTP];
    __shared__ float4 s_wy[OUTP];
    // Per-lane x-tap: column index and x-weight (validity + 0.25 folded in)
    __shared__ int    s_col[28];
    __shared__ float  s_wxw[28];
    __shared__ float  s_x1, s_y1, s_bw, s_bh, s_Hf, s_Wf;
    __shared__ int    s_W, s_HW;
    __shared__ const float* s_base;

    const int blk  = blockIdx.x;             // [0, 512*NGROUPS)
    const int n    = blk >> 4;               // box index [0,512)
    const int g    = blk & (NGROUPS - 1);    // channel group [0,16)
    const int tid  = threadIdx.x;
    const int lane = tid & 31;
    const int wid  = tid >> 5;

    // ---- A: box geometry ----
    if (tid == 0) {
        const int b = n >> 8;
        const float bx1 = boxes[n * 4 + 0];
        const float by1 = boxes[n * 4 + 1];
        const float bx2 = boxes[n * 4 + 2];
        const float by2 = boxes[n * 4 + 3];
        const float area = (bx2 - bx1) * (by2 - by1);
        float lvlf = floorf(4.0f + log2f(sqrtf(area) * (1.0f / 224.0f) + 1e-8f));
        lvlf = fminf(fmaxf(lvlf, 2.0f), 5.0f);
        const int lvl = (int)lvlf - 2;

        int H, W; float scale; const float* fp;
        switch (lvl) {
            case 0:  H = 200; W = 200; scale = 0.25f;    fp = f0; break;
            case 1:  H = 100; W = 100; scale = 0.125f;   fp = f1; break;
            case 2:  H = 50;  W = 50;  scale = 0.0625f;  fp = f2; break;
            default: H = 25;  W = 25;  scale = 0.03125f; fp = f3; break;
        }
        const float x1s = bx1 * scale, y1s = by1 * scale;
        const float x2s = bx2 * scale, y2s = by2 * scale;
        s_x1 = x1s;  s_y1 = y1s;
        s_bw = fmaxf(x2s - x1s, 1.0f) * (1.0f / OUTP);
        s_bh = fmaxf(y2s - y1s, 1.0f) * (1.0f / OUTP);
        s_Hf = (float)H;  s_Wf = (float)W;
        s_W = W;  s_HW = H * W;
        s_base = fp + ((size_t)b * CCH + (size_t)g * CH_PER_CTA) * H * W;
    }
    __syncthreads();

    // ---- B: 28 sample preps (torchvision ROIAlign aligned=False) ----
    if (tid < 2 * NS) {
        const bool is_y = tid < NS;
        const int  i    = is_y ? tid : tid - NS;
        const int  p    = i >> 1;
        const int  s    = i & 1;
        const float gg  = (float)p + ((float)s + 0.5f) * 0.5f;
        const float coord = is_y ? (s_y1 + s_bh * gg) : (s_x1 + s_bw * gg);
        const float lim   = is_y ? s_Hf : s_Wf;

        const float v  = (coord > -1.0f && coord < lim) ? 1.0f : 0.0f;
        float cc  = fmaxf(coord, 0.0f);
        float low = floorf(cc);
        const float cap = lim - 1.0f;
        const bool at_edge = (low >= cap);
        low = fminf(low, cap);
        const float high = fminf(low + 1.0f, cap);
        if (at_edge) cc = low;
        const float frac = cc - low;
        const float w0 = (1.0f - frac) * v;
        const float w1 = frac * v;

        if (is_y) {
            const int W = s_W;
            int*   rop = (int*)s_ro;
            float* wyp = (float*)s_wy;
            rop[4 * (i >> 1) + 2 * (i & 1) + 0] = (int)low  * W;
            rop[4 * (i >> 1) + 2 * (i & 1) + 1] = (int)high * W;
            wyp[4 * (i >> 1) + 2 * (i & 1) + 0] = w0;
            wyp[4 * (i >> 1) + 2 * (i & 1) + 1] = w1;
        } else {
            // fold the final *0.25 (subsample mean) into the x weights
            s_col[2 * i + 0] = (int)low;
            s_col[2 * i + 1] = (int)high;
            s_wxw[2 * i + 0] = w0 * 0.25f;
            s_wxw[2 * i + 1] = w1 * 0.25f;
        }
    }
    __syncthreads();

    // ---- C: compute. warp = 4 channels; lanes = 28 x-taps (4 per bin pw).
    // Lanes 28..31 duplicate tap 27 with zero weight so their addresses stay
    // inside the ROI column span (no extra 128B sector per LDG).
    const int   laneT = (lane < 28) ? lane : 27;
    const int   colb  = s_col[laneT];
    const float wxwb  = (lane < 28) ? s_wxw[laneT] : 0.0f;
    const int   HW    = s_HW;
    const float* const base0 = s_base + (size_t)(wid * 4) * HW + colb;
    float* const out_g = out + (size_t)n * OUT_PER_BOX
                             + (size_t)g * CH_PER_CTA * BINS
                             + (size_t)(wid * 4) * BINS;

    const bool writer = ((lane & 3) == 0) && (lane < 28);
    const int  pw     = lane >> 2;

    // Fully unrolled: lets ptxas hoist next iteration's LDS+LDG into the
    // current iteration's FMA/SHFL reduction (software pipelining).
    #pragma unroll
    for (int ph = 0; ph < OUTP; ++ph) {
        const int4   ro = s_ro[ph];
        const float4 wy = s_wy[ph];

        const float* p0 = base0;
        const float* p1 = base0 + HW;
        const float* p2 = base0 + 2 * HW;
        const float* p3 = base0 + 3 * HW;
        const float v00 = p0[ro.x], v01 = p0[ro.y], v02 = p0[ro.z], v03 = p0[ro.w];
        const float v10 = p1[ro.x], v11 = p1[ro.y], v12 = p1[ro.z], v13 = p1[ro.w];
        const float v20 = p2[ro.x], v21 = p2[ro.y], v22 = p2[ro.z], v23 = p2[ro.w];
        const float v30 = p3[ro.x], v31 = p3[ro.y], v32 = p3[ro.z], v33 = p3[ro.w];

        float a0 = wxwb * (wy.x * v00 + wy.y * v01 + wy.z * v02 + wy.w * v03);
        float a1 = wxwb * (wy.x * v10 + wy.y * v11 + wy.z * v12 + wy.w * v13);
        float a2 = wxwb * (wy.x * v20 + wy.y * v21 + wy.z * v22 + wy.w * v23);
        float a3 = wxwb * (wy.x * v30 + wy.y * v31 + wy.z * v32 + wy.w * v33);

        a0 += __shfl_xor_sync(0xffffffffu, a0, 1);
        a1 += __shfl_xor_sync(0xffffffffu, a1, 1);
        a2 += __shfl_xor_sync(0xffffffffu, a2, 1);
        a3 += __shfl_xor_sync(0xffffffffu, a3, 1);
        a0 += __shfl_xor_sync(0xffffffffu, a0, 2);
        a1 += __shfl_xor_sync(0xffffffffu, a1, 2);
        a2 += __shfl_xor_sync(0xffffffffu, a2, 2);
        a3 += __shfl_xor_sync(0xffffffffu, a3, 2);

        if (writer) {
            const int o = ph * OUTP + pw;
            out_g[0 * BINS + o] = a0;
            out_g[1 * BINS + o] = a1;
            out_g[2 * BINS + o] = a2;
            out_g[3 * BINS + o] = a3;
        }
    }
}

extern "C" void kernel_launch(void* const* d_in, const int* in_sizes, int n_in,
                              void* d_out, int out_size) {
    const float* f0    = (const float*)d_in[0];
    const float* f1    = (const float*)d_in[1];
    const float* f2    = (const float*)d_in[2];
    const float* f3    = (const float*)d_in[3];
    const float* boxes = (const float*)d_in[4];
    float* out = (float*)d_out;

    roi_pooler_kernel<<<512 * NGROUPS, THREADS>>>(f0, f1, f2, f3, boxes, out);
}

// round 13
// speedup vs baseline: 1.0317x; 1.0317x over previous
#include <cuda_runtime.h>
#include <cstdint>

#define OUTP 7
#define CCH 256
#define NS 14                        // samples per axis
#define BINS 49
#define OUT_PER_BOX (CCH * BINS)     // 12544
#define CH_PER_CTA 32
#define NGROUPS (CCH / CH_PER_CTA)   // 8
#define THREADS 256
#define NWARPS (THREADS / 32)        // 8 warps -> 8*4 = 32 channels

__global__ __launch_bounds__(THREADS, 7) void roi_pooler_kernel(
    const float* __restrict__ f0, const float* __restrict__ f1,
    const float* __restrict__ f2, const float* __restrict__ f3,
    const float* __restrict__ boxes, float* __restrict__ out)
{
    // Per-ph packed y-params: 4 row offsets (already *W) and 4 weights
    __shared__ int4   s_ro[OUTP];
    __shared__ float4 s_wy[OUTP];
    // Per-lane x-tap: column index and x-weight (validity + 0.25 folded in)
    __shared__ int    s_col[28];
    __shared__ float  s_wxw[28];
    __shared__ float  s_x1, s_y1, s_bw, s_bh, s_Hf, s_Wf;
    __shared__ int    s_W, s_HW;
    __shared__ const float* s_base;

    const int blk  = blockIdx.x;             // [0, 512*NGROUPS)
    const int n    = blk >> 3;               // box index [0,512)
    const int g    = blk & (NGROUPS - 1);    // channel group [0,8)
    const int tid  = threadIdx.x;
    const int lane = tid & 31;
    const int wid  = tid >> 5;

    // ---- A: box geometry ----
    if (tid == 0) {
        const int b = n >> 8;
        const float bx1 = boxes[n * 4 + 0];
        const float by1 = boxes[n * 4 + 1];
        const float bx2 = boxes[n * 4 + 2];
        const float by2 = boxes[n * 4 + 3];
        const float area = (bx2 - bx1) * (by2 - by1);
        float lvlf = floorf(4.0f + log2f(sqrtf(area) * (1.0f / 224.0f) + 1e-8f));
        lvlf = fminf(fmaxf(lvlf, 2.0f), 5.0f);
        const int lvl = (int)lvlf - 2;

        int H, W; float scale; const float* fp;
        switch (lvl) {
            case 0:  H = 200; W = 200; scale = 0.25f;    fp = f0; break;
            case 1:  H = 100; W = 100; scale = 0.125f;   fp = f1; break;
            case 2:  H = 50;  W = 50;  scale = 0.0625f;  fp = f2; break;
            default: H = 25;  W = 25;  scale = 0.03125f; fp = f3; break;
        }
        const float x1s = bx1 * scale, y1s = by1 * scale;
        const float x2s = bx2 * scale, y2s = by2 * scale;
        s_x1 = x1s;  s_y1 = y1s;
        s_bw = fmaxf(x2s - x1s, 1.0f) * (1.0f / OUTP);
        s_bh = fmaxf(y2s - y1s, 1.0f) * (1.0f / OUTP);
        s_Hf = (float)H;  s_Wf = (float)W;
        s_W = W;  s_HW = H * W;
        s_base = fp + ((size_t)b * CCH + (size_t)g * CH_PER_CTA) * H * W;
    }
    __syncthreads();

    // ---- B: 28 sample preps (torchvision ROIAlign aligned=False) ----
    if (tid < 2 * NS) {
        const bool is_y = tid < NS;
        const int  i    = is_y ? tid : tid - NS;
        const int  p    = i >> 1;
        const int  s    = i & 1;
        const float gg  = (float)p + ((float)s + 0.5f) * 0.5f;
        const float coord = is_y ? (s_y1 + s_bh * gg) : (s_x1 + s_bw * gg);
        const float lim   = is_y ? s_Hf : s_Wf;

        const float v  = (coord > -1.0f && coord < lim) ? 1.0f : 0.0f;
        float cc  = fmaxf(coord, 0.0f);
        float low = floorf(cc);
        const float cap = lim - 1.0f;
        const bool at_edge = (low >= cap);
        low = fminf(low, cap);
        const float high = fminf(low + 1.0f, cap);
        if (at_edge) cc = low;
        const float frac = cc - low;
        const float w0 = (1.0f - frac) * v;
        const float w1 = frac * v;

        if (is_y) {
            const int W = s_W;
            int*   rop = (int*)s_ro;
            float* wyp = (float*)s_wy;
            rop[4 * (i >> 1) + 2 * (i & 1) + 0] = (int)low  * W;
            rop[4 * (i >> 1) + 2 * (i & 1) + 1] = (int)high * W;
            wyp[4 * (i >> 1) + 2 * (i & 1) + 0] = w0;
            wyp[4 * (i >> 1) + 2 * (i & 1) + 1] = w1;
        } else {
            // fold the final *0.25 (subsample mean) into the x weights
            s_col[2 * i + 0] = (int)low;
            s_col[2 * i + 1] = (int)high;
            s_wxw[2 * i + 0] = w0 * 0.25f;
            s_wxw[2 * i + 1] = w1 * 0.25f;
        }
    }
    __syncthreads();

    // ---- C: compute. warp = 4 channels; lanes = 28 x-taps (4 per bin pw).
    // Lanes 28..31 duplicate tap 27 with zero weight so their addresses stay
    // inside the ROI column span (no extra 128B sector per LDG).
    const int   laneT = (lane < 28) ? lane : 27;
    const int   colb  = s_col[laneT];
    const float wxwb  = (lane < 28) ? s_wxw[laneT] : 0.0f;
    const int   HW    = s_HW;
    const float* const base0 = s_base + (size_t)(wid * 4) * HW + colb;
    float* const out_g = out + (size_t)n * OUT_PER_BOX
                             + (size_t)g * CH_PER_CTA * BINS
                             + (size_t)(wid * 4) * BINS;

    const bool writer = ((lane & 3) == 0) && (lane < 28);
    const int  pw     = lane >> 2;

    // Fully unrolled: lets ptxas hoist next iteration's LDS+LDG into the
    // current iteration's FMA/SHFL reduction (software pipelining).
    #pragma unroll
    for (int ph = 0; ph < OUTP; ++ph) {
        const int4   ro = s_ro[ph];
        const float4 wy = s_wy[ph];

        const float* p0 = base0;
        const float* p1 = base0 + HW;
        const float* p2 = base0 + 2 * HW;
        const float* p3 = base0 + 3 * HW;
        const float v00 = p0[ro.x], v01 = p0[ro.y], v02 = p0[ro.z], v03 = p0[ro.w];
        const float v10 = p1[ro.x], v11 = p1[ro.y], v12 = p1[ro.z], v13 = p1[ro.w];
        const float v20 = p2[ro.x], v21 = p2[ro.y], v22 = p2[ro.z], v23 = p2[ro.w];
        const float v30 = p3[ro.x], v31 = p3[ro.y], v32 = p3[ro.z], v33 = p3[ro.w];

        float a0 = wxwb * (wy.x * v00 + wy.y * v01 + wy.z * v02 + wy.w * v03);
        float a1 = wxwb * (wy.x * v10 + wy.y * v11 + wy.z * v12 + wy.w * v13);
        float a2 = wxwb * (wy.x * v20 + wy.y * v21 + wy.z * v22 + wy.w * v23);
        float a3 = wxwb * (wy.x * v30 + wy.y * v31 + wy.z * v32 + wy.w * v33);

        a0 += __shfl_xor_sync(0xffffffffu, a0, 1);
        a1 += __shfl_xor_sync(0xffffffffu, a1, 1);
        a2 += __shfl_xor_sync(0xffffffffu, a2, 1);
        a3 += __shfl_xor_sync(0xffffffffu, a3, 1);
        a0 += __shfl_xor_sync(0xffffffffu, a0, 2);
        a1 += __shfl_xor_sync(0xffffffffu, a1, 2);
        a2 += __shfl_xor_sync(0xffffffffu, a2, 2);
        a3 += __shfl_xor_sync(0xffffffffu, a3, 2);

        if (writer) {
            const int o = ph * OUTP + pw;
            out_g[0 * BINS + o] = a0;
            out_g[1 * BINS + o] = a1;
            out_g[2 * BINS + o] = a2;
            out_g[3 * BINS + o] = a3;
        }
    }
}

extern "C" void kernel_launch(void* const* d_in, const int* in_sizes, int n_in,
                              void* d_out, int out_size) {
    const float* f0    = (const float*)d_in[0];
    const float* f1    = (const float*)d_in[1];
    const float* f2    = (const float*)d_in[2];
    const float* f3    = (const float*)d_in[3];
    const float* boxes = (const float*)d_in[4];
    float* out = (float*)d_out;

    roi_pooler_kernel<<<512 * NGROUPS, THREADS>>>(f0, f1, f2, f3, boxes, out);
}

// round 15
// speedup vs baseline: 1.1348x; 1.0999x over previous
#include <cuda_runtime.h>
#include <cstdint>

#define OUTP 7
#define CCH 256
#define NS 14                        // samples per axis
#define BINS 49
#define OUT_PER_BOX (CCH * BINS)     // 12544
#define CH_PER_CTA 16
#define NGROUPS (CCH / CH_PER_CTA)   // 16
#define THREADS 128
#define NWARPS (THREADS / 32)        // 4 warps -> 4*4 = 16 channels

__global__ __launch_bounds__(THREADS, 12) void roi_pooler_kernel(
    const float* __restrict__ f0, const float* __restrict__ f1,
    const float* __restrict__ f2, const float* __restrict__ f3,
    const float* __restrict__ boxes, float* __restrict__ out)
{
    // Per-ph packed y-params: 4 row offsets (already *W) and 4 weights
    __shared__ int4   s_ro[OUTP];
    __shared__ float4 s_wy[OUTP];
    // Per-lane x-tap: column index and x-weight (validity + 0.25 folded in)
    __shared__ int    s_col[28];
    __shared__ float  s_wxw[28];
    __shared__ float  s_x1, s_y1, s_bw, s_bh, s_Hf, s_Wf;
    __shared__ int    s_W, s_HW;
    __shared__ const float* s_base;

    const int blk  = blockIdx.x;             // [0, 512*NGROUPS)
    const int n    = blk >> 4;               // box index [0,512)
    const int g    = blk & (NGROUPS - 1);    // channel group [0,16)
    const int tid  = threadIdx.x;
    const int lane = tid & 31;
    const int wid  = tid >> 5;

    // ---- A: box geometry ----
    if (tid == 0) {
        const int b = n >> 8;
        const float bx1 = boxes[n * 4 + 0];
        const float by1 = boxes[n * 4 + 1];
        const float bx2 = boxes[n * 4 + 2];
        const float by2 = boxes[n * 4 + 3];
        const float area = (bx2 - bx1) * (by2 - by1);
        float lvlf = floorf(4.0f + log2f(sqrtf(area) * (1.0f / 224.0f) + 1e-8f));
        lvlf = fminf(fmaxf(lvlf, 2.0f), 5.0f);
        const int lvl = (int)lvlf - 2;

        int H, W; float scale; const float* fp;
        switch (lvl) {
            case 0:  H = 200; W = 200; scale = 0.25f;    fp = f0; break;
            case 1:  H = 100; W = 100; scale = 0.125f;   fp = f1; break;
            case 2:  H = 50;  W = 50;  scale = 0.0625f;  fp = f2; break;
            default: H = 25;  W = 25;  scale = 0.03125f; fp = f3; break;
        }
        const float x1s = bx1 * scale, y1s = by1 * scale;
        const float x2s = bx2 * scale, y2s = by2 * scale;
        s_x1 = x1s;  s_y1 = y1s;
        s_bw = fmaxf(x2s - x1s, 1.0f) * (1.0f / OUTP);
        s_bh = fmaxf(y2s - y1s, 1.0f) * (1.0f / OUTP);
        s_Hf = (float)H;  s_Wf = (float)W;
        s_W = W;  s_HW = H * W;
        s_base = fp + ((size_t)b * CCH + (size_t)g * CH_PER_CTA) * H * W;
    }
    __syncthreads();

    // ---- B: 28 sample preps (torchvision ROIAlign aligned=False) ----
    if (tid < 2 * NS) {
        const bool is_y = tid < NS;
        const int  i    = is_y ? tid : tid - NS;
        const int  p    = i >> 1;
        const int  s    = i & 1;
        const float gg  = (float)p + ((float)s + 0.5f) * 0.5f;
        const float coord = is_y ? (s_y1 + s_bh * gg) : (s_x1 + s_bw * gg);
        const float lim   = is_y ? s_Hf : s_Wf;

        const float v  = (coord > -1.0f && coord < lim) ? 1.0f : 0.0f;
        float cc  = fmaxf(coord, 0.0f);
        float low = floorf(cc);
        const float cap = lim - 1.0f;
        const bool at_edge = (low >= cap);
        low = fminf(low, cap);
        const float high = fminf(low + 1.0f, cap);
        if (at_edge) cc = low;
        const float frac = cc - low;
        const float w0 = (1.0f - frac) * v;
        const float w1 = frac * v;

        if (is_y) {
            const int W = s_W;
            int*   rop = (int*)s_ro;
            float* wyp = (float*)s_wy;
            rop[4 * (i >> 1) + 2 * (i & 1) + 0] = (int)low  * W;
            rop[4 * (i >> 1) + 2 * (i & 1) + 1] = (int)high * W;
            wyp[4 * (i >> 1) + 2 * (i & 1) + 0] = w0;
            wyp[4 * (i >> 1) + 2 * (i & 1) + 1] = w1;
        } else {
            // fold the final *0.25 (subsample mean) into the x weights
            s_col[2 * i + 0] = (int)low;
            s_col[2 * i + 1] = (int)high;
            s_wxw[2 * i + 0] = w0 * 0.25f;
            s_wxw[2 * i + 1] = w1 * 0.25f;
        }
    }
    __syncthreads();

    // ---- C: compute. warp = 4 channels; lanes = 28 x-taps (4 per bin pw).
    // Lanes 28..31 duplicate tap 27 with zero weight so their addresses stay
    // inside the ROI column span (no extra 128B sector per LDG).
    const int   laneT = (lane < 28) ? lane : 27;
    const int   colb  = s_col[laneT];
    const float wxwb  = (lane < 28) ? s_wxw[laneT] : 0.0f;
    const int   HW    = s_HW;
    const float* const base0 = s_base + (size_t)(wid * 4) * HW + colb;
    float* const out_g = out + (size_t)n * OUT_PER_BOX
                             + (size_t)g * CH_PER_CTA * BINS
                             + (size_t)(wid * 4) * BINS;

    const bool writer = ((lane & 3) == 0) && (lane < 28);
    const int  pw     = lane >> 2;

    // Fully unrolled: lets ptxas hoist next iteration's LDS+LDG into the
    // current iteration's FMA/SHFL reduction (software pipelining).
    #pragma unroll
    for (int ph = 0; ph < OUTP; ++ph) {
        const int4   ro = s_ro[ph];
        const float4 wy = s_wy[ph];

        const float* p0 = base0;
        const float* p1 = base0 + HW;
        const float* p2 = base0 + 2 * HW;
        const float* p3 = base0 + 3 * HW;
        const float v00 = p0[ro.x], v01 = p0[ro.y], v02 = p0[ro.z], v03 = p0[ro.w];
        const float v10 = p1[ro.x], v11 = p1[ro.y], v12 = p1[ro.z], v13 = p1[ro.w];
        const float v20 = p2[ro.x], v21 = p2[ro.y], v22 = p2[ro.z], v23 = p2[ro.w];
        const float v30 = p3[ro.x], v31 = p3[ro.y], v32 = p3[ro.z], v33 = p3[ro.w];

        float a0 = wxwb * (wy.x * v00 + wy.y * v01 + wy.z * v02 + wy.w * v03);
        float a1 = wxwb * (wy.x * v10 + wy.y * v11 + wy.z * v12 + wy.w * v13);
        float a2 = wxwb * (wy.x * v20 + wy.y * v21 + wy.z * v22 + wy.w * v23);
        float a3 = wxwb * (wy.x * v30 + wy.y * v31 + wy.z * v32 + wy.w * v33);

        a0 += __shfl_xor_sync(0xffffffffu, a0, 1);
        a1 += __shfl_xor_sync(0xffffffffu, a1, 1);
        a2 += __shfl_xor_sync(0xffffffffu, a2, 1);
        a3 += __shfl_xor_sync(0xffffffffu, a3, 1);
        a0 += __shfl_xor_sync(0xffffffffu, a0, 2);
        a1 += __shfl_xor_sync(0xffffffffu, a1, 2);
        a2 += __shfl_xor_sync(0xffffffffu, a2, 2);
        a3 += __shfl_xor_sync(0xffffffffu, a3, 2);

        if (writer) {
            const int o = ph * OUTP + pw;
            out_g[0 * BINS + o] = a0;
            out_g[1 * BINS + o] = a1;
            out_g[2 * BINS + o] = a2;
            out_g[3 * BINS + o] = a3;
        }
    }
}

extern "C" void kernel_launch(void* const* d_in, const int* in_sizes, int n_in,
                              void* d_out, int out_size) {
    const float* f0    = (const float*)d_in[0];
    const float* f1    = (const float*)d_in[1];
    const float* f2    = (const float*)d_in[2];
    const float* f3    = (const float*)d_in[3];
    const float* boxes = (const float*)d_in[4];
    float* out = (float*)d_out;

    roi_pooler_kernel<<<512 * NGROUPS, THREADS>>>(f0, f1, f2, f3, boxes, out);
}

// round 16
// speedup vs baseline: 1.1428x; 1.0070x over previous
#include <cuda_runtime.h>
#include <cstdint>

#define OUTP 7
#define CCH 256
#define NS 14                        // samples per axis
#define BINS 49
#define OUT_PER_BOX (CCH * BINS)     // 12544
#define CH_PER_CTA 16
#define NGROUPS (CCH / CH_PER_CTA)   // 16
#define THREADS 128
#define NWARPS (THREADS / 32)        // 4 warps -> 4*4 = 16 channels

// Level-specialized body: H, W, HW are compile-time so channel offsets fold
// into LDG immediates (no per-load IADD) and prep multiplies are by constants.
template<int H, int W>
__device__ __forceinline__ void roi_body(
    const float* __restrict__ base, float* __restrict__ out_g,
    int4* s_ro, float4* s_wy, int* s_col, float* s_wxw,
    const float* s_geom,            // [x1, y1, bw, bh]
    int tid, int lane, int wid)
{
    constexpr int HW = H * W;

    // ---- B: 28 sample preps (torchvision ROIAlign aligned=False) ----
    if (tid < 2 * NS) {
        const bool is_y = tid < NS;
        const int  i    = is_y ? tid : tid - NS;
        const int  p    = i >> 1;
        const int  s    = i & 1;
        const float gg  = (float)p + ((float)s + 0.5f) * 0.5f;
        const float coord = is_y ? (s_geom[1] + s_geom[3] * gg)
                                 : (s_geom[0] + s_geom[2] * gg);
        const float lim   = is_y ? (float)H : (float)W;

        const float v  = (coord > -1.0f && coord < lim) ? 1.0f : 0.0f;
        float cc  = fmaxf(coord, 0.0f);
        float low = floorf(cc);
        const float cap = lim - 1.0f;
        const bool at_edge = (low >= cap);
        low = fminf(low, cap);
        const float high = fminf(low + 1.0f, cap);
        if (at_edge) cc = low;
        const float frac = cc - low;
        const float w0 = (1.0f - frac) * v;
        const float w1 = frac * v;

        if (is_y) {
            int*   rop = (int*)s_ro;
            float* wyp = (float*)s_wy;
            rop[4 * (i >> 1) + 2 * (i & 1) + 0] = (int)low  * W;
            rop[4 * (i >> 1) + 2 * (i & 1) + 1] = (int)high * W;
            wyp[4 * (i >> 1) + 2 * (i & 1) + 0] = w0;
            wyp[4 * (i >> 1) + 2 * (i & 1) + 1] = w1;
        } else {
            // fold the final *0.25 (subsample mean) into the x weights
            s_col[2 * i + 0] = (int)low;
            s_col[2 * i + 1] = (int)high;
            s_wxw[2 * i + 0] = w0 * 0.25f;
            s_wxw[2 * i + 1] = w1 * 0.25f;
        }
    }
    __syncthreads();

    // ---- C: compute. warp = 4 channels; lanes = 28 x-taps (4 per bin pw).
    // Lanes 28..31 duplicate tap 27 with zero weight so their addresses stay
    // inside the ROI column span (no extra 128B sector per LDG).
    const int   laneT = (lane < 28) ? lane : 27;
    const int   colb  = s_col[laneT];
    const float wxwb  = (lane < 28) ? s_wxw[laneT] : 0.0f;
    const float* const base0 = base + (size_t)(wid * 4) * HW + colb;

    const bool writer = ((lane & 3) == 0) && (lane < 28);
    const int  pw     = lane >> 2;

    // Fully unrolled: lets ptxas hoist next iteration's LDS+LDG into the
    // current iteration's FMA/SHFL reduction (software pipelining). The
    // k*HW channel offsets are compile-time -> LDG immediates.
    #pragma unroll
    for (int ph = 0; ph < OUTP; ++ph) {
        const int4   ro = s_ro[ph];
        const float4 wy = s_wy[ph];

        const float v00 = base0[ro.x + 0 * HW], v01 = base0[ro.y + 0 * HW],
                    v02 = base0[ro.z + 0 * HW], v03 = base0[ro.w + 0 * HW];
        const float v10 = base0[ro.x + 1 * HW], v11 = base0[ro.y + 1 * HW],
                    v12 = base0[ro.z + 1 * HW], v13 = base0[ro.w + 1 * HW];
        const float v20 = base0[ro.x + 2 * HW], v21 = base0[ro.y + 2 * HW],
                    v22 = base0[ro.z + 2 * HW], v23 = base0[ro.w + 2 * HW];
        const float v30 = base0[ro.x + 3 * HW], v31 = base0[ro.y + 3 * HW],
                    v32 = base0[ro.z + 3 * HW], v33 = base0[ro.w + 3 * HW];

        float a0 = wxwb * (wy.x * v00 + wy.y * v01 + wy.z * v02 + wy.w * v03);
        float a1 = wxwb * (wy.x * v10 + wy.y * v11 + wy.z * v12 + wy.w * v13);
        float a2 = wxwb * (wy.x * v20 + wy.y * v21 + wy.z * v22 + wy.w * v23);
        float a3 = wxwb * (wy.x * v30 + wy.y * v31 + wy.z * v32 + wy.w * v33);

        a0 += __shfl_xor_sync(0xffffffffu, a0, 1);
        a1 += __shfl_xor_sync(0xffffffffu, a1, 1);
        a2 += __shfl_xor_sync(0xffffffffu, a2, 1);
        a3 += __shfl_xor_sync(0xffffffffu, a3, 1);
        a0 += __shfl_xor_sync(0xffffffffu, a0, 2);
        a1 += __shfl_xor_sync(0xffffffffu, a1, 2);
        a2 += __shfl_xor_sync(0xffffffffu, a2, 2);
        a3 += __shfl_xor_sync(0xffffffffu, a3, 2);

        if (writer) {
            const int o = ph * OUTP + pw;
            out_g[0 * BINS + o] = a0;
            out_g[1 * BINS + o] = a1;
            out_g[2 * BINS + o] = a2;
            out_g[3 * BINS + o] = a3;
        }
    }
}

__global__ __launch_bounds__(THREADS, 12) void roi_pooler_kernel(
    const float* __restrict__ f0, const float* __restrict__ f1,
    const float* __restrict__ f2, const float* __restrict__ f3,
    const float* __restrict__ boxes, float* __restrict__ out)
{
    __shared__ int4   s_ro[OUTP];
    __shared__ float4 s_wy[OUTP];
    __shared__ int    s_col[28];
    __shared__ float  s_wxw[28];
    __shared__ float  s_geom[4];       // x1, y1, bw, bh
    __shared__ int    s_lvl;
    __shared__ const float* s_base;

    const int blk  = blockIdx.x;             // [0, 512*NGROUPS)
    const int n    = blk >> 4;               // box index [0,512)
    const int g    = blk & (NGROUPS - 1);    // channel group [0,16)
    const int tid  = threadIdx.x;
    const int lane = tid & 31;
    const int wid  = tid >> 5;

    // ---- A: box geometry + level selection ----
    if (tid == 0) {
        const int b = n >> 8;
        const float bx1 = boxes[n * 4 + 0];
        const float by1 = boxes[n * 4 + 1];
        const float bx2 = boxes[n * 4 + 2];
        const float by2 = boxes[n * 4 + 3];
        const float area = (bx2 - bx1) * (by2 - by1);
        float lvlf = floorf(4.0f + log2f(sqrtf(area) * (1.0f / 224.0f) + 1e-8f));
        lvlf = fminf(fmaxf(lvlf, 2.0f), 5.0f);
        const int lvl = (int)lvlf - 2;

        int H, W; float scale; const float* fp;
        switch (lvl) {
            case 0:  H = 200; W = 200; scale = 0.25f;    fp = f0; break;
            case 1:  H = 100; W = 100; scale = 0.125f;   fp = f1; break;
            case 2:  H = 50;  W = 50;  scale = 0.0625f;  fp = f2; break;
            default: H = 25;  W = 25;  scale = 0.03125f; fp = f3; break;
        }
        const float x1s = bx1 * scale, y1s = by1 * scale;
        const float x2s = bx2 * scale, y2s = by2 * scale;
        s_geom[0] = x1s;
        s_geom[1] = y1s;
        s_geom[2] = fmaxf(x2s - x1s, 1.0f) * (1.0f / OUTP);
        s_geom[3] = fmaxf(y2s - y1s, 1.0f) * (1.0f / OUTP);
        s_lvl  = lvl;
        s_base = fp + ((size_t)b * CCH + (size_t)g * CH_PER_CTA) * H * W;
    }
    __syncthreads();

    const float* const base = s_base;
    float* const out_g = out + (size_t)n * OUT_PER_BOX
                             + (size_t)g * CH_PER_CTA * BINS
                             + (size_t)(wid * 4) * BINS;

    // CTA-uniform branch (same lvl for all threads) -> barriers inside are legal.
    switch (s_lvl) {
        case 0:
            roi_body<200, 200>(base, out_g, s_ro, s_wy, s_col, s_wxw, s_geom, tid, lane, wid);
            break;
        case 1:
            roi_body<100, 100>(base, out_g, s_ro, s_wy, s_col, s_wxw, s_geom, tid, lane, wid);
            break;
        case 2:
            roi_body<50, 50>(base, out_g, s_ro, s_wy, s_col, s_wxw, s_geom, tid, lane, wid);
            break;
        default:
            roi_body<25, 25>(base, out_g, s_ro, s_wy, s_col, s_wxw, s_geom, tid, lane, wid);
            break;
    }
}

extern "C" void kernel_launch(void* const* d_in, const int* in_sizes, int n_in,
                              void* d_out, int out_size) {
    const float* f0    = (const float*)d_in[0];
    const float* f1    = (const float*)d_in[1];
    const float* f2    = (const float*)d_in[2];
    const float* f3    = (const float*)d_in[3];
    const float* boxes = (const float*)d_in[4];
    float* out = (float*)d_out;

    roi_pooler_kernel<<<512 * NGROUPS, THREADS>>>(f0, f1, f2, f3, boxes, out);
}